// round 10
// baseline (speedup 1.0000x reference)
#include <cuda_runtime.h>

// out[row, f] = x[row, f] * sf^2,  sf = sum_m w_m(t) * coeffs[i-3+m, f]
// i = floor(eig*7.5), t = frac  (uniform knots linspace(0,2,16), cubic
// cardinal B-spline -> exactly 4 nonzero weights).
//
// R10: coefficient table cached in REGISTERS (12 x float4 per thread = its 4
// channels), selected by a warp-uniform switch(i). Removes the 16 LDS
// wavefronts/row that capped every previous round at ~34 cyc/row.
// No shared memory, no barrier. R6-style RPI=2 prefetch pipeline retained.

#define F_CH 128
#define N_BASES 12
#define RPI 2

// accumulate sf over real coeff rows j0..j1 with weights starting at wm0
#define TERM(j, wm) do { \
    sf.x += (wm) * cc[j].x; sf.y += (wm) * cc[j].y; \
    sf.z += (wm) * cc[j].z; sf.w += (wm) * cc[j].w; } while (0)

__global__ __launch_bounds__(128, 5)
void spline_filter_kernel(const float* __restrict__ x,
                          const float* __restrict__ eig,
                          const float* __restrict__ coef,
                          float* __restrict__ out,
                          int nrows)
{
    const int lane = threadIdx.x & 31;

    // ---- register-cached coeff slice: 12 rows x this thread's 4 channels ----
    float4 cc[N_BASES];
    #pragma unroll
    for (int j = 0; j < N_BASES; j++)
        cc[j] = __ldg((const float4*)(coef + j * F_CH) + lane);

    const int warp    = (blockIdx.x << 2) + (threadIdx.x >> 5);
    const int wstride = gridDim.x << 2;

    int row = warp * RPI;
    if (row >= nrows) return;

    float2 e  = *(const float2*)(eig + row);
    float4 xa = __ldcs((const float4*)(x + (size_t)row * F_CH) + lane);
    float4 xb = __ldcs((const float4*)(x + (size_t)(row + 1) * F_CH) + lane);

    while (true) {
        const int nrow = row + wstride * RPI;
        const bool nvalid = nrow < nrows;

        float2 ne; float4 nxa, nxb;
        if (nvalid) {
            ne  = *(const float2*)(eig + nrow);
            nxa = __ldcs((const float4*)(x + (size_t)nrow * F_CH) + lane);
            nxb = __ldcs((const float4*)(x + (size_t)(nrow + 1) * F_CH) + lane);
        }

        #pragma unroll
        for (int k = 0; k < RPI; k++) {
            float ev  = (k == 0) ? e.x : e.y;
            float4 xv = (k == 0) ? xa  : xb;

            float s  = ev * 7.5f;
            float fi = floorf(s);
            int   i  = min(max((int)fi, 0), 14);
            float t  = s - (float)i;
            float omt = 1.0f - t;
            float t2  = t * t;
            float w0 = omt * omt * omt * (1.0f / 6.0f);
            float w1 = ((3.0f * t - 6.0f) * t2 + 4.0f) * (1.0f / 6.0f);
            float w2 = (((-3.0f * t + 3.0f) * t + 3.0f) * t + 1.0f) * (1.0f / 6.0f);
            float w3 = t * t2 * (1.0f / 6.0f);

            // sf = w0*C[i-3] + w1*C[i-2] + w2*C[i-1] + w3*C[i], rows <0 / >11 are zero.
            // i is warp-uniform -> switch compiles to a non-divergent indirect branch.
            float4 sf = make_float4(0.f, 0.f, 0.f, 0.f);
            switch (i) {
                case 0:  TERM(0, w3); break;
                case 1:  TERM(0, w2); TERM(1, w3); break;
                case 2:  TERM(0, w1); TERM(1, w2); TERM(2, w3); break;
                case 3:  TERM(0, w0); TERM(1, w1); TERM(2, w2); TERM(3, w3); break;
                case 4:  TERM(1, w0); TERM(2, w1); TERM(3, w2); TERM(4, w3); break;
                case 5:  TERM(2, w0); TERM(3, w1); TERM(4, w2); TERM(5, w3); break;
                case 6:  TERM(3, w0); TERM(4, w1); TERM(5, w2); TERM(6, w3); break;
                case 7:  TERM(4, w0); TERM(5, w1); TERM(6, w2); TERM(7, w3); break;
                case 8:  TERM(5, w0); TERM(6, w1); TERM(7, w2); TERM(8, w3); break;
                case 9:  TERM(6, w0); TERM(7, w1); TERM(8, w2); TERM(9, w3); break;
                case 10: TERM(7, w0); TERM(8, w1); TERM(9, w2); TERM(10, w3); break;
                case 11: TERM(8, w0); TERM(9, w1); TERM(10, w2); TERM(11, w3); break;
                case 12: TERM(9, w0); TERM(10, w1); TERM(11, w2); break;
                case 13: TERM(10, w0); TERM(11, w1); break;
                default: TERM(11, w0); break;  // i == 14
            }

            float4 ov;
            ov.x = xv.x * sf.x * sf.x;
            ov.y = xv.y * sf.y * sf.y;
            ov.z = xv.z * sf.z * sf.z;
            ov.w = xv.w * sf.w * sf.w;

            __stcs((float4*)(out + (size_t)(row + k) * F_CH) + lane, ov);
        }

        if (!nvalid) break;
        e = ne; xa = nxa; xb = nxb; row = nrow;
    }
}

extern "C" void kernel_launch(void* const* d_in, const int* in_sizes, int n_in,
                              void* d_out, int out_size)
{
    const float* x    = (const float*)d_in[0];  // eval_x        [B,N,128] f32
    const float* eig  = (const float*)d_in[1];  // eval_eigs     [B,N]     f32
    const float* coef = (const float*)d_in[2];  // filter_coeffs [12,128]  f32
    float* out = (float*)d_out;

    int nrows = in_sizes[0] / F_CH;             // B*N = 262144
    // 4 warps/block, 5 blocks/SM resident -> 740 blocks = single wave.
    int blocks = 740;
    int need = (nrows + (4 * RPI) - 1) / (4 * RPI);
    if (blocks > need) blocks = need;
    spline_filter_kernel<<<blocks, 128>>>(x, eig, coef, out, nrows);
}

// round 13
// speedup vs baseline: 1.1383x; 1.1383x over previous
#include <cuda_runtime.h>

// out[row, f] = x[row, f] * sf^2,  sf = sum_m w_m(t) * coeffs[i-3+m, f]
// i = floor(eig*7.5), t = frac  (uniform knots linspace(0,2,16), cubic
// cardinal B-spline -> exactly 4 nonzero weights).
//
// R11: R6 pipeline but prefetch ONLY the x rows (eig read in-loop; it's a
// 1 MB L2-resident stream) and cap regs via __launch_bounds__(256,6) so
// occupancy recovers to ~75% while keeping ~1KB/warp of reads in flight.

#define F_CH 128
#define N_BASES 12
#define PAD_ROWS 18  // padded rows -3..14 -> 0..17; i in [0,14] => i+3 <= 17
#define RPI 2        // rows per warp-iteration (eig loaded as one float2)

__global__ __launch_bounds__(256, 6)
void spline_filter_kernel(const float* __restrict__ x,
                          const float* __restrict__ eig,
                          const float* __restrict__ coef,
                          float* __restrict__ out,
                          int nrows)
{
    __shared__ float sc[PAD_ROWS * F_CH];  // zero-padded coeff table, 9 KB

    // Cooperative fill: padded rows [0,3) and [15,18) zero, rows 3..14 = coeffs.
    #pragma unroll
    for (int idx = threadIdx.x; idx < PAD_ROWS * F_CH; idx += 256) {
        int j = (idx >> 7) - 3;
        sc[idx] = (j >= 0 && j < N_BASES) ? coef[idx - 3 * F_CH] : 0.0f;
    }
    __syncthreads();

    const int lane    = threadIdx.x & 31;
    const int warp    = (blockIdx.x << 3) + (threadIdx.x >> 5);
    const int wstride = gridDim.x << 3;
    const float* scl  = sc + lane * 4;   // per-lane channel base in smem

    int row = warp * RPI;
    if (row >= nrows) return;

    // ---- prologue: load first pair of x rows ----
    float4 xa = __ldcs((const float4*)(x + (size_t)row * F_CH) + lane);
    float4 xb = __ldcs((const float4*)(x + (size_t)(row + 1) * F_CH) + lane);

    while (true) {
        const int nrow = row + wstride * RPI;
        const bool nvalid = nrow < nrows;

        // ---- prefetch next x rows only (keeps reg count low) ----
        float4 nxa, nxb;
        if (nvalid) {
            nxa = __ldcs((const float4*)(x + (size_t)nrow * F_CH) + lane);
            nxb = __ldcs((const float4*)(x + (size_t)(nrow + 1) * F_CH) + lane);
        }

        // eig read in-loop: tiny stream, L2-resident, overlapped by warps
        float2 e = *(const float2*)(eig + row);

        // ---- compute + store current pair ----
        #pragma unroll
        for (int k = 0; k < RPI; k++) {
            float ev  = (k == 0) ? e.x : e.y;
            float4 xv = (k == 0) ? xa  : xb;

            float s  = ev * 7.5f;
            float fi = floorf(s);
            int   i  = min(max((int)fi, 0), 14);
            float t  = s - (float)i;
            float omt = 1.0f - t;
            float t2  = t * t;
            float w0 = omt * omt * omt * (1.0f / 6.0f);
            float w1 = ((3.0f * t - 6.0f) * t2 + 4.0f) * (1.0f / 6.0f);
            float w2 = (((-3.0f * t + 3.0f) * t + 3.0f) * t + 1.0f) * (1.0f / 6.0f);
            float w3 = t * t2 * (1.0f / 6.0f);

            const float4* p = (const float4*)(scl + i * F_CH);
            float4 a = p[0];       // row i
            float4 b = p[32];      // row i+1  (+512 B)
            float4 c = p[64];      // row i+2  (+1024 B)
            float4 d = p[96];      // row i+3  (+1536 B)

            float4 sf;
            sf.x = w0 * a.x + w1 * b.x + w2 * c.x + w3 * d.x;
            sf.y = w0 * a.y + w1 * b.y + w2 * c.y + w3 * d.y;
            sf.z = w0 * a.z + w1 * b.z + w2 * c.z + w3 * d.z;
            sf.w = w0 * a.w + w1 * b.w + w2 * c.w + w3 * d.w;

            float4 ov;
            ov.x = xv.x * sf.x * sf.x;
            ov.y = xv.y * sf.y * sf.y;
            ov.z = xv.z * sf.z * sf.z;
            ov.w = xv.w * sf.w * sf.w;

            __stcs((float4*)(out + (size_t)(row + k) * F_CH) + lane, ov);
        }

        if (!nvalid) break;
        xa = nxa; xb = nxb; row = nrow;
    }
}

extern "C" void kernel_launch(void* const* d_in, const int* in_sizes, int n_in,
                              void* d_out, int out_size)
{
    const float* x    = (const float*)d_in[0];  // eval_x        [B,N,128] f32
    const float* eig  = (const float*)d_in[1];  // eval_eigs     [B,N]     f32
    const float* coef = (const float*)d_in[2];  // filter_coeffs [12,128]  f32
    float* out = (float*)d_out;

    int nrows = in_sizes[0] / F_CH;             // B*N = 262144
    // 8 warps/block, 2 rows per warp-iteration, 2048 blocks
    // -> 8 pipelined iterations per warp.
    int blocks = 2048;
    int need = (nrows + (8 * RPI) - 1) / (8 * RPI);
    if (blocks > need) blocks = need;
    spline_filter_kernel<<<blocks, 256>>>(x, eig, coef, out, nrows);
}